// round 11
// baseline (speedup 1.0000x reference)
#include <cuda_runtime.h>
#include <cuda_bf16.h>

// ---------------------------------------------------------------------------
// HypernymVisual: h = relu(vfs)@W1 + b1 ; e = relu(h)@W2 + b2 ;
// scores[n,l] = -sqrt(sum_d relu(lv[l,d] - e[n,d])^2)
//
// Round 11: score kernel restructured thread=n. e rows live in REGISTERS
// (loaded once, coalesced via transposed g_enegT); lv loads are warp-uniform
// LDG.128 (1 wavefront, L1-hit: block's 54KB l-chunk is L1-resident).
// ---------------------------------------------------------------------------

#define NV   256
#define DV   4096
#define DH   1024
#define DE   100
#define LL   20000
#define SPL1 8      // gemm1 K splits (512 cols each)
#define SPL2 16     // gemm2 K splits (64 cols each)
#define LCHUNK 136  // l per block: 148 blocks, 136 and tail both /4

typedef unsigned long long u64;

// scratch (device globals)
__device__ uint4 g_Ah4[NV * DV / 8];   // bf16 [256][4096]  hi(relu(vfs))
__device__ uint4 g_Al4[NV * DV / 8];   // bf16 [256][4096]  lo residual
__device__ uint4 g_Bh4[DH * DV / 8];   // bf16 [1024 n][4096 k]  hi(W1^T)
__device__ uint4 g_Bl4[DH * DV / 8];   // bf16 [1024 n][4096 k]  lo residual
__device__ float g_hp[SPL1][NV * DH];  // gemm1 K-split partials (no bias)
__device__ float g_ep[SPL2][NV * DE];  // gemm2 K-split partials (no bias)
__device__ u64 g_enegT[50 * NV];       // -(e) transposed: [d-pair][n]

// ---- f32x2 helpers ---------------------------------------------------------
__device__ __forceinline__ u64 f2add(u64 a, u64 b) {
    u64 r; asm("add.rn.f32x2 %0,%1,%2;" : "=l"(r) : "l"(a), "l"(b)); return r;
}
__device__ __forceinline__ u64 f2fma(u64 a, u64 b, u64 c) {
    u64 r; asm("fma.rn.f32x2 %0,%1,%2,%3;" : "=l"(r) : "l"(a), "l"(b), "l"(c)); return r;
}
__device__ __forceinline__ u64 f2relu(u64 x) {
    u64 r;
    asm("{\n\t"
        ".reg .s32 lo, hi;\n\t"
        "mov.b64 {lo, hi}, %1;\n\t"
        "max.s32 lo, lo, 0;\n\t"
        "max.s32 hi, hi, 0;\n\t"
        "mov.b64 %0, {lo, hi};\n\t"
        "}" : "=l"(r) : "l"(x));
    return r;
}
__device__ __forceinline__ u64 fpack(float x, float y) {
    u64 r;
    unsigned lo = __float_as_uint(x), hi = __float_as_uint(y);
    asm("mov.b64 %0,{%1,%2};" : "=l"(r) : "r"(lo), "r"(hi));
    return r;
}
__device__ __forceinline__ float2 funpack(u64 a) {
    unsigned lo, hi;
    asm("mov.b64 {%0,%1},%2;" : "=r"(lo), "=r"(hi) : "l"(a));
    return make_float2(__uint_as_float(lo), __uint_as_float(hi));
}
__device__ __forceinline__ float fsqrt_ap(float x) {
    float r; asm("sqrt.approx.f32 %0,%1;" : "=f"(r) : "f"(x)); return r;
}

// ---- bf16 mma --------------------------------------------------------------
__device__ __forceinline__ void mma_bf16(float d[4], const unsigned a[4],
                                         const unsigned b[2]) {
    asm("mma.sync.aligned.m16n8k16.row.col.f32.bf16.bf16.f32 "
        "{%0,%1,%2,%3},{%4,%5,%6,%7},{%8,%9},{%0,%1,%2,%3};"
        : "+f"(d[0]), "+f"(d[1]), "+f"(d[2]), "+f"(d[3])
        : "r"(a[0]), "r"(a[1]), "r"(a[2]), "r"(a[3]), "r"(b[0]), "r"(b[1]));
}

// ---------------------------------------------------------------------------
// prep_all: blocks [0,1024): A = relu(vfs) -> bf16 hi/lo, [m][k]
//           blocks [1024,5120): W1 -> transposed bf16 hi/lo [n][k]
// ---------------------------------------------------------------------------
__global__ __launch_bounds__(256) void prep_all(
    const float* __restrict__ vfs, const float* __restrict__ W1)
{
    if (blockIdx.x < 1024) {
        int i = blockIdx.x * 256 + threadIdx.x;        // float4 index
        float4 v = ((const float4*)vfs)[i];
        v.x = fmaxf(v.x, 0.f); v.y = fmaxf(v.y, 0.f);
        v.z = fmaxf(v.z, 0.f); v.w = fmaxf(v.w, 0.f);
        __nv_bfloat16 h0 = __float2bfloat16(v.x);
        __nv_bfloat16 h1 = __float2bfloat16(v.y);
        __nv_bfloat16 h2 = __float2bfloat16(v.z);
        __nv_bfloat16 h3 = __float2bfloat16(v.w);
        __nv_bfloat16 l0 = __float2bfloat16(v.x - __bfloat162float(h0));
        __nv_bfloat16 l1 = __float2bfloat16(v.y - __bfloat162float(h1));
        __nv_bfloat16 l2 = __float2bfloat16(v.z - __bfloat162float(h2));
        __nv_bfloat16 l3 = __float2bfloat16(v.w - __bfloat162float(h3));
        __nv_bfloat162* ph = (__nv_bfloat162*)g_Ah4;
        __nv_bfloat162* pl = (__nv_bfloat162*)g_Al4;
        ph[i * 2 + 0] = __nv_bfloat162{h0, h1};
        ph[i * 2 + 1] = __nv_bfloat162{h2, h3};
        pl[i * 2 + 0] = __nv_bfloat162{l0, l1};
        pl[i * 2 + 1] = __nv_bfloat162{l2, l3};
    } else {
        __shared__ float tile[32][33];
        const int bx = blockIdx.x - 1024;
        const int k0 = (bx & 127) * 32, n0 = (bx >> 7) * 32;
        const int t = threadIdx.x;
        const int nc = t & 31, kr0 = t >> 5;
#pragma unroll
        for (int i = 0; i < 4; ++i) {
            int kr = kr0 + i * 8;
            tile[kr][nc] = W1[(size_t)(k0 + kr) * DH + n0 + nc];
        }
        __syncthreads();
        const int i = t >> 3, j0 = (t & 7) * 4;
        __nv_bfloat16 hs[4], ls[4];
#pragma unroll
        for (int jj = 0; jj < 4; ++jj) {
            float x = tile[j0 + jj][i];
            __nv_bfloat16 h = __float2bfloat16(x);
            hs[jj] = h;
            ls[jj] = __float2bfloat16(x - __bfloat162float(h));
        }
        size_t off = (size_t)(n0 + i) * DV + k0 + j0;
        __nv_bfloat162* ph = (__nv_bfloat162*)((__nv_bfloat16*)g_Bh4 + off);
        __nv_bfloat162* pl = (__nv_bfloat162*)((__nv_bfloat16*)g_Bl4 + off);
        ph[0] = __nv_bfloat162{hs[0], hs[1]};
        ph[1] = __nv_bfloat162{hs[2], hs[3]};
        pl[0] = __nv_bfloat162{ls[0], ls[1]};
        pl[1] = __nv_bfloat162{ls[2], ls[3]};
    }
}

// ---------------------------------------------------------------------------
// gemm1_tc: g_hp[z][m][n] = A_slice @ B_slice with bf16 split-2 compensation
// CTA tile M64 x N128, 8 warps (2m x 4n), warp tile 32x32, K chunk 32.
// grid (8 n, 4 m, SPL1=8 z) = 256 CTAs; K-slice 512 = 16 chunks.
// ---------------------------------------------------------------------------
__global__ __launch_bounds__(256, 2) void gemm1_tc(int dummy)
{
    __shared__ unsigned short sAh[2][64][40], sAl[2][64][40];
    __shared__ unsigned short sBh[2][128][40], sBl[2][128][40];

    const int t = threadIdx.x;
    const int lane = t & 31, warp = t >> 5;
    const int g = lane >> 2, tq = lane & 3;
    const int wm = warp & 1, wn = warp >> 1;
    const int m0 = blockIdx.y * 64, n0 = blockIdx.x * 128;
    const size_t kb0 = (size_t)blockIdx.z * 512;

    const __nv_bfloat16* Ah = (const __nv_bfloat16*)g_Ah4;
    const __nv_bfloat16* Al = (const __nv_bfloat16*)g_Al4;
    const __nv_bfloat16* Bh = (const __nv_bfloat16*)g_Bh4;
    const __nv_bfloat16* Bl = (const __nv_bfloat16*)g_Bl4;

    const int ldRow  = t >> 2;            // 0..63
    const int ldPart = (t & 3) * 8;       // bf16 elems
    const size_t aOff  = (size_t)(m0 + ldRow) * DV + kb0 + ldPart;
    const size_t bOff1 = (size_t)(n0 + ldRow) * DV + kb0 + ldPart;
    const size_t bOff2 = (size_t)(n0 + 64 + ldRow) * DV + kb0 + ldPart;

    float d[2][4][4];
#pragma unroll
    for (int mf = 0; mf < 2; ++mf)
#pragma unroll
        for (int nf = 0; nf < 4; ++nf)
#pragma unroll
            for (int r = 0; r < 4; ++r) d[mf][nf][r] = 0.f;

    {
        uint4 pAh  = *(const uint4*)(Ah + aOff);
        uint4 pAl  = *(const uint4*)(Al + aOff);
        uint4 pB1h = *(const uint4*)(Bh + bOff1);
        uint4 pB2h = *(const uint4*)(Bh + bOff2);
        uint4 pB1l = *(const uint4*)(Bl + bOff1);
        uint4 pB2l = *(const uint4*)(Bl + bOff2);
        *(uint4*)&sAh[0][ldRow][ldPart] = pAh;
        *(uint4*)&sAl[0][ldRow][ldPart] = pAl;
        *(uint4*)&sBh[0][ldRow][ldPart] = pB1h;
        *(uint4*)&sBh[0][64 + ldRow][ldPart] = pB2h;
        *(uint4*)&sBl[0][ldRow][ldPart] = pB1l;
        *(uint4*)&sBl[0][64 + ldRow][ldPart] = pB2l;
    }
    __syncthreads();

    for (int c = 0; c < 16; ++c) {
        const int cur = c & 1;
        const int nxt = cur ^ 1;

        uint4 pAh, pAl, pB1h, pB2h, pB1l, pB2l;
        if (c < 15) {
            size_t kd = (size_t)(c + 1) * 32;
            pAh  = *(const uint4*)(Ah + aOff + kd);
            pAl  = *(const uint4*)(Al + aOff + kd);
            pB1h = *(const uint4*)(Bh + bOff1 + kd);
            pB2h = *(const uint4*)(Bh + bOff2 + kd);
            pB1l = *(const uint4*)(Bl + bOff1 + kd);
            pB2l = *(const uint4*)(Bl + bOff2 + kd);
        }

#pragma unroll
        for (int s = 0; s < 2; ++s) {
            const int kc = s * 16 + 2 * tq;
            unsigned ah[2][4], al[2][4], bh[4][2], bl[4][2];
#pragma unroll
            for (int mf = 0; mf < 2; ++mf) {
                int r = wm * 32 + mf * 16 + g;
                ah[mf][0] = *(const unsigned*)&sAh[cur][r][kc];
                ah[mf][1] = *(const unsigned*)&sAh[cur][r + 8][kc];
                ah[mf][2] = *(const unsigned*)&sAh[cur][r][kc + 8];
                ah[mf][3] = *(const unsigned*)&sAh[cur][r + 8][kc + 8];
                al[mf][0] = *(const unsigned*)&sAl[cur][r][kc];
                al[mf][1] = *(const unsigned*)&sAl[cur][r + 8][kc];
                al[mf][2] = *(const unsigned*)&sAl[cur][r][kc + 8];
                al[mf][3] = *(const unsigned*)&sAl[cur][r + 8][kc + 8];
            }
#pragma unroll
            for (int nf = 0; nf < 4; ++nf) {
                int n = wn * 32 + nf * 8 + g;
                bh[nf][0] = *(const unsigned*)&sBh[cur][n][kc];
                bh[nf][1] = *(const unsigned*)&sBh[cur][n][kc + 8];
                bl[nf][0] = *(const unsigned*)&sBl[cur][n][kc];
                bl[nf][1] = *(const unsigned*)&sBl[cur][n][kc + 8];
            }
#pragma unroll
            for (int nf = 0; nf < 4; ++nf)
#pragma unroll
                for (int mf = 0; mf < 2; ++mf)
                    mma_bf16(d[mf][nf], ah[mf], bh[nf]);
#pragma unroll
            for (int nf = 0; nf < 4; ++nf)
#pragma unroll
                for (int mf = 0; mf < 2; ++mf)
                    mma_bf16(d[mf][nf], ah[mf], bl[nf]);
#pragma unroll
            for (int nf = 0; nf < 4; ++nf)
#pragma unroll
                for (int mf = 0; mf < 2; ++mf)
                    mma_bf16(d[mf][nf], al[mf], bh[nf]);
        }

        if (c < 15) {
            *(uint4*)&sAh[nxt][ldRow][ldPart] = pAh;
            *(uint4*)&sAl[nxt][ldRow][ldPart] = pAl;
            *(uint4*)&sBh[nxt][ldRow][ldPart] = pB1h;
            *(uint4*)&sBh[nxt][64 + ldRow][ldPart] = pB2h;
            *(uint4*)&sBl[nxt][ldRow][ldPart] = pB1l;
            *(uint4*)&sBl[nxt][64 + ldRow][ldPart] = pB2l;
        }
        __syncthreads();
    }

    float* outp = g_hp[blockIdx.z];
#pragma unroll
    for (int mf = 0; mf < 2; ++mf)
#pragma unroll
        for (int nf = 0; nf < 4; ++nf) {
            int m = m0 + wm * 32 + mf * 16 + g;
            int n = n0 + wn * 32 + nf * 8 + 2 * tq;
            *(float2*)&outp[(size_t)m * DH + n] =
                make_float2(d[mf][nf][0], d[mf][nf][1]);
            *(float2*)&outp[(size_t)(m + 8) * DH + n] =
                make_float2(d[mf][nf][2], d[mf][nf][3]);
        }
}

// ---------------------------------------------------------------------------
// GEMM2: g_ep[s] = relu(sum_z g_hp[z] + b1) @ W2  over 64-wide k-slice s
// grid (16, SPL2=16) = 256 blocks
// ---------------------------------------------------------------------------
__global__ __launch_bounds__(256) void gemm2_kernel(
    const float* __restrict__ W2, const float* __restrict__ b1)
{
    __shared__ __align__(16) float sh_h[16 * 64];
    __shared__ float sh_w[64 * 112];

    const int t = threadIdx.x;
    const int m0 = blockIdx.x * 16;
    const int kc = blockIdx.y * 64;
    const int tm = t >> 4, tj = t & 15;

    float acc[7];
#pragma unroll
    for (int u = 0; u < 7; ++u) acc[u] = 0.f;

    {
        int idx = t * 4;
        int m = idx >> 6, kk = idx & 63;
        size_t off = (size_t)(m0 + m) * DH + kc + kk;
        float4 hv = *(const float4*)(b1 + kc + kk);
#pragma unroll
        for (int z = 0; z < SPL1; ++z) {
            float4 p = *(const float4*)(g_hp[z] + off);
            hv.x += p.x; hv.y += p.y; hv.z += p.z; hv.w += p.w;
        }
        hv.x = fmaxf(hv.x, 0.f);
        hv.y = fmaxf(hv.y, 0.f);
        hv.z = fmaxf(hv.z, 0.f);
        hv.w = fmaxf(hv.w, 0.f);
        *(float4*)&sh_h[m * 64 + kk] = hv;
    }
#pragma unroll
    for (int r = 0; r < 25; ++r) {
        int idx = r * 256 + t;
        int kk = idx / 100;
        int j  = idx - kk * 100;
        sh_w[kk * 112 + j] = W2[(size_t)(kc + kk) * DE + j];
    }
    __syncthreads();

#pragma unroll 8
    for (int kk = 0; kk < 64; ++kk) {
        float a = sh_h[tm * 64 + kk];
#pragma unroll
        for (int u = 0; u < 7; ++u)
            acc[u] += a * sh_w[kk * 112 + tj + 16 * u];
    }
    __syncthreads();

    float* ep = g_ep[blockIdx.y];
#pragma unroll
    for (int u = 0; u < 7; ++u) {
        int j = tj + 16 * u;
        if (j < DE) ep[(size_t)(m0 + tm) * DE + j] = acc[u];
    }
}

// ---------------------------------------------------------------------------
// finalize_e: g_enegT[pair][n] = packed -(b2 + sum_s g_ep[s]) pairs
// grid 25 blocks x 256 threads (6400 float4s, each -> 2 u64 pairs)
// ---------------------------------------------------------------------------
__global__ __launch_bounds__(256) void finalize_e(const float* __restrict__ b2)
{
    int idx = blockIdx.x * 256 + threadIdx.x;     // 0..6399 (float4 index)
    int n = idx / 25;
    int d4 = idx - n * 25;
    float4 v = ((const float4*)b2)[d4];
#pragma unroll
    for (int s = 0; s < SPL2; ++s) {
        float4 p = ((const float4*)g_ep[s])[idx];
        v.x += p.x; v.y += p.y; v.z += p.z; v.w += p.w;
    }
    g_enegT[(2 * d4 + 0) * NV + n] = fpack(-v.x, -v.y);
    g_enegT[(2 * d4 + 1) * NV + n] = fpack(-v.z, -v.w);
}

// ---------------------------------------------------------------------------
// Scoring: out[n,l] = -sqrt( sum_d relu(lv[l,d] - e[n,d])^2 )
// thread = n (256 threads = all n). Block owns a 136-l chunk (L1-resident).
// e row in registers (50 u64). lv reads are warp-uniform LDG.128 (1 wf).
// grid 148 blocks.
// ---------------------------------------------------------------------------
__global__ __launch_bounds__(256, 1) void score_kernel(
    const float* __restrict__ lv, float* __restrict__ out)
{
    const int n = threadIdx.x;
    const int l_begin = blockIdx.x * LCHUNK;
    const int l_end   = min(l_begin + LCHUNK, LL);

    // e pairs: coalesced loads from transposed layout
    u64 ep[50];
#pragma unroll
    for (int p = 0; p < 50; ++p) ep[p] = g_enegT[p * NV + n];

    float* orow = out + (size_t)n * LL;

    for (int lg = l_begin; lg < l_end; lg += 4) {
        const ulonglong2* r0 = (const ulonglong2*)(lv + (size_t)(lg + 0) * DE);
        const ulonglong2* r1 = (const ulonglong2*)(lv + (size_t)(lg + 1) * DE);
        const ulonglong2* r2 = (const ulonglong2*)(lv + (size_t)(lg + 2) * DE);
        const ulonglong2* r3 = (const ulonglong2*)(lv + (size_t)(lg + 3) * DE);

        u64 acc0 = 0, acc1 = 0, acc2 = 0, acc3 = 0;

#pragma unroll
        for (int q = 0; q < 25; ++q) {
            ulonglong2 v0 = __ldg(&r0[q]);
            ulonglong2 v1 = __ldg(&r1[q]);
            ulonglong2 v2 = __ldg(&r2[q]);
            ulonglong2 v3 = __ldg(&r3[q]);
            u64 e0 = ep[2 * q], e1 = ep[2 * q + 1];
            u64 t0, t1, t2, t3;
            t0 = f2relu(f2add(v0.x, e0)); acc0 = f2fma(t0, t0, acc0);
            t1 = f2relu(f2add(v1.x, e0)); acc1 = f2fma(t1, t1, acc1);
            t2 = f2relu(f2add(v2.x, e0)); acc2 = f2fma(t2, t2, acc2);
            t3 = f2relu(f2add(v3.x, e0)); acc3 = f2fma(t3, t3, acc3);
            t0 = f2relu(f2add(v0.y, e1)); acc0 = f2fma(t0, t0, acc0);
            t1 = f2relu(f2add(v1.y, e1)); acc1 = f2fma(t1, t1, acc1);
            t2 = f2relu(f2add(v2.y, e1)); acc2 = f2fma(t2, t2, acc2);
            t3 = f2relu(f2add(v3.y, e1)); acc3 = f2fma(t3, t3, acc3);
        }

        float2 s0 = funpack(acc0), s1 = funpack(acc1);
        float2 s2 = funpack(acc2), s3 = funpack(acc3);
        float4 res;
        res.x = -fsqrt_ap(s0.x + s0.y);
        res.y = -fsqrt_ap(s1.x + s1.y);
        res.z = -fsqrt_ap(s2.x + s2.y);
        res.w = -fsqrt_ap(s3.x + s3.y);
        *(float4*)&orow[lg] = res;
    }
}

// ---------------------------------------------------------------------------
extern "C" void kernel_launch(void* const* d_in, const int* in_sizes, int n_in,
                              void* d_out, int out_size)
{
    const float* vfs = (const float*)d_in[0];   // [256, 4096]
    const float* lv  = (const float*)d_in[1];   // [20000, 100]
    const float* W1  = (const float*)d_in[2];   // [4096, 1024]
    const float* b1  = (const float*)d_in[3];   // [1024]
    const float* W2  = (const float*)d_in[4];   // [1024, 100]
    const float* b2  = (const float*)d_in[5];   // [100]
    float* out = (float*)d_out;                 // [256, 20000]

    prep_all<<<1024 + 4096, 256>>>(vfs, W1);
    gemm1_tc<<<dim3(8, 4, SPL1), 256>>>(0);
    gemm2_kernel<<<dim3(16, SPL2), 256>>>(W2, b1);
    finalize_e<<<25, 256>>>(b2);
    score_kernel<<<148, 256>>>(lv, out);
}

// round 12
// speedup vs baseline: 1.3211x; 1.3211x over previous
#include <cuda_runtime.h>
#include <cuda_bf16.h>

// ---------------------------------------------------------------------------
// HypernymVisual: h = relu(vfs)@W1 + b1 ; e = relu(h)@W2 + b2 ;
// scores[n,l] = -sqrt(sum_d relu(lv[l,d] - e[n,d])^2)
//
// Round 12: score kernel stages the lv tile in SMEM (contiguous copy in,
// conflict-free LDS.128 out — 400B row stride = odd 16B-granule stride).
// Replaces the 32-wavefront lv LDG scatter with 4 wf. NN=16, occ 2.
// ---------------------------------------------------------------------------

#define NV   256
#define DV   4096
#define DH   1024
#define DE   100
#define LL   20000
#define SPL1 8      // gemm1 K splits (512 cols each)
#define SPL2 16     // gemm2 K splits (64 cols each)

typedef unsigned long long u64;

// scratch (device globals)
__device__ uint4 g_Ah4[NV * DV / 8];   // bf16 [256][4096]  hi(relu(vfs))
__device__ uint4 g_Al4[NV * DV / 8];   // bf16 [256][4096]  lo residual
__device__ uint4 g_Bh4[DH * DV / 8];   // bf16 [1024 n][4096 k]  hi(W1^T)
__device__ uint4 g_Bl4[DH * DV / 8];   // bf16 [1024 n][4096 k]  lo residual
__device__ float g_hp[SPL1][NV * DH];  // gemm1 K-split partials (no bias)
__device__ float g_ep[SPL2][NV * DE];  // gemm2 K-split partials (no bias)
__device__ __align__(16) float g_eneg[NV * DE];  // -(e) final embeddings

// ---- f32x2 helpers ---------------------------------------------------------
__device__ __forceinline__ u64 f2add(u64 a, u64 b) {
    u64 r; asm("add.rn.f32x2 %0,%1,%2;" : "=l"(r) : "l"(a), "l"(b)); return r;
}
__device__ __forceinline__ u64 f2fma(u64 a, u64 b, u64 c) {
    u64 r; asm("fma.rn.f32x2 %0,%1,%2,%3;" : "=l"(r) : "l"(a), "l"(b), "l"(c)); return r;
}
__device__ __forceinline__ u64 f2relu(u64 x) {
    u64 r;
    asm("{\n\t"
        ".reg .s32 lo, hi;\n\t"
        "mov.b64 {lo, hi}, %1;\n\t"
        "max.s32 lo, lo, 0;\n\t"
        "max.s32 hi, hi, 0;\n\t"
        "mov.b64 %0, {lo, hi};\n\t"
        "}" : "=l"(r) : "l"(x));
    return r;
}
__device__ __forceinline__ float2 funpack(u64 a) {
    unsigned lo, hi;
    asm("mov.b64 {%0,%1},%2;" : "=r"(lo), "=r"(hi) : "l"(a));
    return make_float2(__uint_as_float(lo), __uint_as_float(hi));
}
__device__ __forceinline__ float fsqrt_ap(float x) {
    float r; asm("sqrt.approx.f32 %0,%1;" : "=f"(r) : "f"(x)); return r;
}

// ---- bf16 mma --------------------------------------------------------------
__device__ __forceinline__ void mma_bf16(float d[4], const unsigned a[4],
                                         const unsigned b[2]) {
    asm("mma.sync.aligned.m16n8k16.row.col.f32.bf16.bf16.f32 "
        "{%0,%1,%2,%3},{%4,%5,%6,%7},{%8,%9},{%0,%1,%2,%3};"
        : "+f"(d[0]), "+f"(d[1]), "+f"(d[2]), "+f"(d[3])
        : "r"(a[0]), "r"(a[1]), "r"(a[2]), "r"(a[3]), "r"(b[0]), "r"(b[1]));
}

// ---------------------------------------------------------------------------
// prep_all: blocks [0,1024): A = relu(vfs) -> bf16 hi/lo, [m][k]
//           blocks [1024,5120): W1 -> transposed bf16 hi/lo [n][k]
// ---------------------------------------------------------------------------
__global__ __launch_bounds__(256) void prep_all(
    const float* __restrict__ vfs, const float* __restrict__ W1)
{
    if (blockIdx.x < 1024) {
        int i = blockIdx.x * 256 + threadIdx.x;        // float4 index
        float4 v = ((const float4*)vfs)[i];
        v.x = fmaxf(v.x, 0.f); v.y = fmaxf(v.y, 0.f);
        v.z = fmaxf(v.z, 0.f); v.w = fmaxf(v.w, 0.f);
        __nv_bfloat16 h0 = __float2bfloat16(v.x);
        __nv_bfloat16 h1 = __float2bfloat16(v.y);
        __nv_bfloat16 h2 = __float2bfloat16(v.z);
        __nv_bfloat16 h3 = __float2bfloat16(v.w);
        __nv_bfloat16 l0 = __float2bfloat16(v.x - __bfloat162float(h0));
        __nv_bfloat16 l1 = __float2bfloat16(v.y - __bfloat162float(h1));
        __nv_bfloat16 l2 = __float2bfloat16(v.z - __bfloat162float(h2));
        __nv_bfloat16 l3 = __float2bfloat16(v.w - __bfloat162float(h3));
        __nv_bfloat162* ph = (__nv_bfloat162*)g_Ah4;
        __nv_bfloat162* pl = (__nv_bfloat162*)g_Al4;
        ph[i * 2 + 0] = __nv_bfloat162{h0, h1};
        ph[i * 2 + 1] = __nv_bfloat162{h2, h3};
        pl[i * 2 + 0] = __nv_bfloat162{l0, l1};
        pl[i * 2 + 1] = __nv_bfloat162{l2, l3};
    } else {
        __shared__ float tile[32][33];
        const int bx = blockIdx.x - 1024;
        const int k0 = (bx & 127) * 32, n0 = (bx >> 7) * 32;
        const int t = threadIdx.x;
        const int nc = t & 31, kr0 = t >> 5;
#pragma unroll
        for (int i = 0; i < 4; ++i) {
            int kr = kr0 + i * 8;
            tile[kr][nc] = W1[(size_t)(k0 + kr) * DH + n0 + nc];
        }
        __syncthreads();
        const int i = t >> 3, j0 = (t & 7) * 4;
        __nv_bfloat16 hs[4], ls[4];
#pragma unroll
        for (int jj = 0; jj < 4; ++jj) {
            float x = tile[j0 + jj][i];
            __nv_bfloat16 h = __float2bfloat16(x);
            hs[jj] = h;
            ls[jj] = __float2bfloat16(x - __bfloat162float(h));
        }
        size_t off = (size_t)(n0 + i) * DV + k0 + j0;
        __nv_bfloat162* ph = (__nv_bfloat162*)((__nv_bfloat16*)g_Bh4 + off);
        __nv_bfloat162* pl = (__nv_bfloat162*)((__nv_bfloat16*)g_Bl4 + off);
        ph[0] = __nv_bfloat162{hs[0], hs[1]};
        ph[1] = __nv_bfloat162{hs[2], hs[3]};
        pl[0] = __nv_bfloat162{ls[0], ls[1]};
        pl[1] = __nv_bfloat162{ls[2], ls[3]};
    }
}

// ---------------------------------------------------------------------------
// gemm1_tc: g_hp[z][m][n] = A_slice @ B_slice with bf16 split-2 compensation
// CTA tile M64 x N128, 8 warps (2m x 4n), warp tile 32x32, K chunk 32.
// grid (8 n, 4 m, SPL1=8 z) = 256 CTAs; K-slice 512 = 16 chunks.
// ---------------------------------------------------------------------------
__global__ __launch_bounds__(256, 2) void gemm1_tc(int dummy)
{
    __shared__ unsigned short sAh[2][64][40], sAl[2][64][40];
    __shared__ unsigned short sBh[2][128][40], sBl[2][128][40];

    const int t = threadIdx.x;
    const int lane = t & 31, warp = t >> 5;
    const int g = lane >> 2, tq = lane & 3;
    const int wm = warp & 1, wn = warp >> 1;
    const int m0 = blockIdx.y * 64, n0 = blockIdx.x * 128;
    const size_t kb0 = (size_t)blockIdx.z * 512;

    const __nv_bfloat16* Ah = (const __nv_bfloat16*)g_Ah4;
    const __nv_bfloat16* Al = (const __nv_bfloat16*)g_Al4;
    const __nv_bfloat16* Bh = (const __nv_bfloat16*)g_Bh4;
    const __nv_bfloat16* Bl = (const __nv_bfloat16*)g_Bl4;

    const int ldRow  = t >> 2;            // 0..63
    const int ldPart = (t & 3) * 8;       // bf16 elems
    const size_t aOff  = (size_t)(m0 + ldRow) * DV + kb0 + ldPart;
    const size_t bOff1 = (size_t)(n0 + ldRow) * DV + kb0 + ldPart;
    const size_t bOff2 = (size_t)(n0 + 64 + ldRow) * DV + kb0 + ldPart;

    float d[2][4][4];
#pragma unroll
    for (int mf = 0; mf < 2; ++mf)
#pragma unroll
        for (int nf = 0; nf < 4; ++nf)
#pragma unroll
            for (int r = 0; r < 4; ++r) d[mf][nf][r] = 0.f;

    {
        uint4 pAh  = *(const uint4*)(Ah + aOff);
        uint4 pAl  = *(const uint4*)(Al + aOff);
        uint4 pB1h = *(const uint4*)(Bh + bOff1);
        uint4 pB2h = *(const uint4*)(Bh + bOff2);
        uint4 pB1l = *(const uint4*)(Bl + bOff1);
        uint4 pB2l = *(const uint4*)(Bl + bOff2);
        *(uint4*)&sAh[0][ldRow][ldPart] = pAh;
        *(uint4*)&sAl[0][ldRow][ldPart] = pAl;
        *(uint4*)&sBh[0][ldRow][ldPart] = pB1h;
        *(uint4*)&sBh[0][64 + ldRow][ldPart] = pB2h;
        *(uint4*)&sBl[0][ldRow][ldPart] = pB1l;
        *(uint4*)&sBl[0][64 + ldRow][ldPart] = pB2l;
    }
    __syncthreads();

    for (int c = 0; c < 16; ++c) {
        const int cur = c & 1;
        const int nxt = cur ^ 1;

        uint4 pAh, pAl, pB1h, pB2h, pB1l, pB2l;
        if (c < 15) {
            size_t kd = (size_t)(c + 1) * 32;
            pAh  = *(const uint4*)(Ah + aOff + kd);
            pAl  = *(const uint4*)(Al + aOff + kd);
            pB1h = *(const uint4*)(Bh + bOff1 + kd);
            pB2h = *(const uint4*)(Bh + bOff2 + kd);
            pB1l = *(const uint4*)(Bl + bOff1 + kd);
            pB2l = *(const uint4*)(Bl + bOff2 + kd);
        }

#pragma unroll
        for (int s = 0; s < 2; ++s) {
            const int kc = s * 16 + 2 * tq;
            unsigned ah[2][4], al[2][4], bh[4][2], bl[4][2];
#pragma unroll
            for (int mf = 0; mf < 2; ++mf) {
                int r = wm * 32 + mf * 16 + g;
                ah[mf][0] = *(const unsigned*)&sAh[cur][r][kc];
                ah[mf][1] = *(const unsigned*)&sAh[cur][r + 8][kc];
                ah[mf][2] = *(const unsigned*)&sAh[cur][r][kc + 8];
                ah[mf][3] = *(const unsigned*)&sAh[cur][r + 8][kc + 8];
                al[mf][0] = *(const unsigned*)&sAl[cur][r][kc];
                al[mf][1] = *(const unsigned*)&sAl[cur][r + 8][kc];
                al[mf][2] = *(const unsigned*)&sAl[cur][r][kc + 8];
                al[mf][3] = *(const unsigned*)&sAl[cur][r + 8][kc + 8];
            }
#pragma unroll
            for (int nf = 0; nf < 4; ++nf) {
                int n = wn * 32 + nf * 8 + g;
                bh[nf][0] = *(const unsigned*)&sBh[cur][n][kc];
                bh[nf][1] = *(const unsigned*)&sBh[cur][n][kc + 8];
                bl[nf][0] = *(const unsigned*)&sBl[cur][n][kc];
                bl[nf][1] = *(const unsigned*)&sBl[cur][n][kc + 8];
            }
#pragma unroll
            for (int nf = 0; nf < 4; ++nf)
#pragma unroll
                for (int mf = 0; mf < 2; ++mf)
                    mma_bf16(d[mf][nf], ah[mf], bh[nf]);
#pragma unroll
            for (int nf = 0; nf < 4; ++nf)
#pragma unroll
                for (int mf = 0; mf < 2; ++mf)
                    mma_bf16(d[mf][nf], ah[mf], bl[nf]);
#pragma unroll
            for (int nf = 0; nf < 4; ++nf)
#pragma unroll
                for (int mf = 0; mf < 2; ++mf)
                    mma_bf16(d[mf][nf], al[mf], bh[nf]);
        }

        if (c < 15) {
            *(uint4*)&sAh[nxt][ldRow][ldPart] = pAh;
            *(uint4*)&sAl[nxt][ldRow][ldPart] = pAl;
            *(uint4*)&sBh[nxt][ldRow][ldPart] = pB1h;
            *(uint4*)&sBh[nxt][64 + ldRow][ldPart] = pB2h;
            *(uint4*)&sBl[nxt][ldRow][ldPart] = pB1l;
            *(uint4*)&sBl[nxt][64 + ldRow][ldPart] = pB2l;
        }
        __syncthreads();
    }

    float* outp = g_hp[blockIdx.z];
#pragma unroll
    for (int mf = 0; mf < 2; ++mf)
#pragma unroll
        for (int nf = 0; nf < 4; ++nf) {
            int m = m0 + wm * 32 + mf * 16 + g;
            int n = n0 + wn * 32 + nf * 8 + 2 * tq;
            *(float2*)&outp[(size_t)m * DH + n] =
                make_float2(d[mf][nf][0], d[mf][nf][1]);
            *(float2*)&outp[(size_t)(m + 8) * DH + n] =
                make_float2(d[mf][nf][2], d[mf][nf][3]);
        }
}

// ---------------------------------------------------------------------------
// GEMM2: g_ep[s] = relu(sum_z g_hp[z] + b1) @ W2  over 64-wide k-slice s
// grid (16, SPL2=16) = 256 blocks
// ---------------------------------------------------------------------------
__global__ __launch_bounds__(256) void gemm2_kernel(
    const float* __restrict__ W2, const float* __restrict__ b1)
{
    __shared__ __align__(16) float sh_h[16 * 64];
    __shared__ float sh_w[64 * 112];

    const int t = threadIdx.x;
    const int m0 = blockIdx.x * 16;
    const int kc = blockIdx.y * 64;
    const int tm = t >> 4, tj = t & 15;

    float acc[7];
#pragma unroll
    for (int u = 0; u < 7; ++u) acc[u] = 0.f;

    {
        int idx = t * 4;
        int m = idx >> 6, kk = idx & 63;
        size_t off = (size_t)(m0 + m) * DH + kc + kk;
        float4 hv = *(const float4*)(b1 + kc + kk);
#pragma unroll
        for (int z = 0; z < SPL1; ++z) {
            float4 p = *(const float4*)(g_hp[z] + off);
            hv.x += p.x; hv.y += p.y; hv.z += p.z; hv.w += p.w;
        }
        hv.x = fmaxf(hv.x, 0.f);
        hv.y = fmaxf(hv.y, 0.f);
        hv.z = fmaxf(hv.z, 0.f);
        hv.w = fmaxf(hv.w, 0.f);
        *(float4*)&sh_h[m * 64 + kk] = hv;
    }
#pragma unroll
    for (int r = 0; r < 25; ++r) {
        int idx = r * 256 + t;
        int kk = idx / 100;
        int j  = idx - kk * 100;
        sh_w[kk * 112 + j] = W2[(size_t)(kc + kk) * DE + j];
    }
    __syncthreads();

#pragma unroll 8
    for (int kk = 0; kk < 64; ++kk) {
        float a = sh_h[tm * 64 + kk];
#pragma unroll
        for (int u = 0; u < 7; ++u)
            acc[u] += a * sh_w[kk * 112 + tj + 16 * u];
    }
    __syncthreads();

    float* ep = g_ep[blockIdx.y];
#pragma unroll
    for (int u = 0; u < 7; ++u) {
        int j = tj + 16 * u;
        if (j < DE) ep[(size_t)(m0 + tm) * DE + j] = acc[u];
    }
}

// ---------------------------------------------------------------------------
// finalize_e: g_eneg = -(b2 + sum_s g_ep[s]), float4-wide (6400 float4s)
// ---------------------------------------------------------------------------
__global__ __launch_bounds__(256) void finalize_e(const float* __restrict__ b2)
{
    int idx = blockIdx.x * 256 + threadIdx.x;     // 0..6399 (float4 index)
    int n = idx / 25;
    int d4 = idx - n * 25;
    float4 v = ((const float4*)b2)[d4];
#pragma unroll
    for (int s = 0; s < SPL2; ++s) {
        float4 p = ((const float4*)g_ep[s])[idx];
        v.x += p.x; v.y += p.y; v.z += p.z; v.w += p.w;
    }
    ((float4*)g_eneg)[idx] = make_float4(-v.x, -v.y, -v.z, -v.w);
}

// ---------------------------------------------------------------------------
// Scoring: out[n,l] = -sqrt( sum_d relu(lv[l,d] - e[n,d])^2 )
// lv tile (256 l x 100 floats = 100KB) staged in dynamic smem: contiguous
// copy in, conflict-free LDS.128 out (row stride 400B = 25 x 16B, odd).
// thread = local l; NN=16 n per thread, e via broadcast LDS.128.
// grid (ceil(20000/256)=79, 16 n-tiles) = 1264 blocks, occ 2.
// ---------------------------------------------------------------------------
__global__ __launch_bounds__(256, 2) void score_kernel(
    const float* __restrict__ lv, float* __restrict__ out)
{
    extern __shared__ __align__(16) float lvs[];   // [256][100] contiguous
    __shared__ __align__(16) float e_s[16 * DE];

    const int t  = threadIdx.x;
    const int n0 = blockIdx.y * 16;
    const int l0 = blockIdx.x * 256;

    // e tile: 1600 floats = 400 float4 (contiguous copy)
    {
        const float4* src = (const float4*)(g_eneg + n0 * DE);
        float4* dst = (float4*)e_s;
        dst[t] = src[t];
        if (t < 144) dst[256 + t] = src[256 + t];
    }
    // lv tile: 256 rows x 400B = 6400 uint4, contiguous (25x16B = 400B rows)
    {
        const uint4* src = (const uint4*)(lv + (size_t)l0 * DE);
        uint4* dst = (uint4*)lvs;
        if (l0 + 256 <= LL) {
#pragma unroll
            for (int k = 0; k < 25; ++k)
                dst[t + k * 256] = src[t + k * 256];
        } else {
            const int maxu4 = (LL - l0) * 25;
#pragma unroll
            for (int k = 0; k < 25; ++k) {
                int i = t + k * 256;
                dst[i] = (i < maxu4) ? src[i] : make_uint4(0u, 0u, 0u, 0u);
            }
        }
    }
    __syncthreads();

    const ulonglong2* myrow = (const ulonglong2*)(lvs + t * DE);
    const u64* es2 = (const u64*)e_s;   // [n][50] d-pairs

    u64 acc[16];
#pragma unroll
    for (int n = 0; n < 16; ++n) acc[n] = 0ull;

    ulonglong2 a = myrow[0];
#pragma unroll 1
    for (int q = 0; q < 25; ++q) {
        ulonglong2 na = myrow[(q < 24) ? (q + 1) : 24];
        const int dp = q << 1;
#pragma unroll
        for (int n = 0; n < 16; ++n) {
            ulonglong2 e4 = *(const ulonglong2*)&es2[n * 50 + dp];  // bcast
            u64 t0 = f2relu(f2add(a.x, e4.x));
            acc[n] = f2fma(t0, t0, acc[n]);
            u64 t1 = f2relu(f2add(a.y, e4.y));
            acc[n] = f2fma(t1, t1, acc[n]);
        }
        a = na;
    }

    const int l = l0 + t;
    if (l < LL) {
#pragma unroll
        for (int n = 0; n < 16; ++n) {
            float2 v = funpack(acc[n]);
            out[(size_t)(n0 + n) * LL + l] = -fsqrt_ap(v.x + v.y);
        }
    }
}

// ---------------------------------------------------------------------------
extern "C" void kernel_launch(void* const* d_in, const int* in_sizes, int n_in,
                              void* d_out, int out_size)
{
    const float* vfs = (const float*)d_in[0];   // [256, 4096]
    const float* lv  = (const float*)d_in[1];   // [20000, 100]
    const float* W1  = (const float*)d_in[2];   // [4096, 1024]
    const float* b1  = (const float*)d_in[3];   // [1024]
    const float* W2  = (const float*)d_in[4];   // [1024, 100]
    const float* b2  = (const float*)d_in[5];   // [100]
    float* out = (float*)d_out;                 // [256, 20000]

    const int lv_smem = 256 * DE * (int)sizeof(float);   // 102400 B
    cudaFuncSetAttribute(score_kernel,
                         cudaFuncAttributeMaxDynamicSharedMemorySize, lv_smem);

    prep_all<<<1024 + 4096, 256>>>(vfs, W1);
    gemm1_tc<<<dim3(8, 4, SPL1), 256>>>(0);
    gemm2_kernel<<<dim3(16, SPL2), 256>>>(W2, b1);
    finalize_e<<<25, 256>>>(b2);
    score_kernel<<<dim3(79, 16), 256, lv_smem>>>(lv, out);
}

// round 13
// speedup vs baseline: 1.3946x; 1.0557x over previous
#include <cuda_runtime.h>
#include <cuda_bf16.h>

// ---------------------------------------------------------------------------
// HypernymVisual: h = relu(vfs)@W1 + b1 ; e = relu(h)@W2 + b2 ;
// scores[n,l] = -sqrt(sum_d relu(lv[l,d] - e[n,d])^2)
//
// Round 13: score kernel register-tiled NL=4 x NN=8 — cuts L1 data-return
// traffic from 4.25 to 1.5 B/scalar (the invariant ~60us wall across R5/R8/
// R12 was LDS.128 register-writeback at 128 B/cyc/SM, broadcast included).
// ---------------------------------------------------------------------------

#define NV   256
#define DV   4096
#define DH   1024
#define DE   100
#define LL   20000
#define SPL1 8      // gemm1 K splits (512 cols each)
#define SPL2 16     // gemm2 K splits (64 cols each)

typedef unsigned long long u64;

// scratch (device globals)
__device__ uint4 g_Ah4[NV * DV / 8];   // bf16 [256][4096]  hi(relu(vfs))
__device__ uint4 g_Al4[NV * DV / 8];   // bf16 [256][4096]  lo residual
__device__ uint4 g_Bh4[DH * DV / 8];   // bf16 [1024 n][4096 k]  hi(W1^T)
__device__ uint4 g_Bl4[DH * DV / 8];   // bf16 [1024 n][4096 k]  lo residual
__device__ float g_hp[SPL1][NV * DH];  // gemm1 K-split partials (no bias)
__device__ float g_ep[SPL2][NV * DE];  // gemm2 K-split partials (no bias)
__device__ __align__(16) float g_eneg[NV * DE];  // -(e) final embeddings

// ---- f32x2 helpers ---------------------------------------------------------
__device__ __forceinline__ u64 f2add(u64 a, u64 b) {
    u64 r; asm("add.rn.f32x2 %0,%1,%2;" : "=l"(r) : "l"(a), "l"(b)); return r;
}
__device__ __forceinline__ u64 f2fma(u64 a, u64 b, u64 c) {
    u64 r; asm("fma.rn.f32x2 %0,%1,%2,%3;" : "=l"(r) : "l"(a), "l"(b), "l"(c)); return r;
}
__device__ __forceinline__ u64 f2relu(u64 x) {
    u64 r;
    asm("{\n\t"
        ".reg .s32 lo, hi;\n\t"
        "mov.b64 {lo, hi}, %1;\n\t"
        "max.s32 lo, lo, 0;\n\t"
        "max.s32 hi, hi, 0;\n\t"
        "mov.b64 %0, {lo, hi};\n\t"
        "}" : "=l"(r) : "l"(x));
    return r;
}
__device__ __forceinline__ float2 funpack(u64 a) {
    unsigned lo, hi;
    asm("mov.b64 {%0,%1},%2;" : "=r"(lo), "=r"(hi) : "l"(a));
    return make_float2(__uint_as_float(lo), __uint_as_float(hi));
}
__device__ __forceinline__ float fsqrt_ap(float x) {
    float r; asm("sqrt.approx.f32 %0,%1;" : "=f"(r) : "f"(x)); return r;
}

// ---- bf16 mma --------------------------------------------------------------
__device__ __forceinline__ void mma_bf16(float d[4], const unsigned a[4],
                                         const unsigned b[2]) {
    asm("mma.sync.aligned.m16n8k16.row.col.f32.bf16.bf16.f32 "
        "{%0,%1,%2,%3},{%4,%5,%6,%7},{%8,%9},{%0,%1,%2,%3};"
        : "+f"(d[0]), "+f"(d[1]), "+f"(d[2]), "+f"(d[3])
        : "r"(a[0]), "r"(a[1]), "r"(a[2]), "r"(a[3]), "r"(b[0]), "r"(b[1]));
}

// ---------------------------------------------------------------------------
// prep_all: blocks [0,1024): A = relu(vfs) -> bf16 hi/lo, [m][k]
//           blocks [1024,5120): W1 -> transposed bf16 hi/lo [n][k]
// ---------------------------------------------------------------------------
__global__ __launch_bounds__(256) void prep_all(
    const float* __restrict__ vfs, const float* __restrict__ W1)
{
    if (blockIdx.x < 1024) {
        int i = blockIdx.x * 256 + threadIdx.x;        // float4 index
        float4 v = ((const float4*)vfs)[i];
        v.x = fmaxf(v.x, 0.f); v.y = fmaxf(v.y, 0.f);
        v.z = fmaxf(v.z, 0.f); v.w = fmaxf(v.w, 0.f);
        __nv_bfloat16 h0 = __float2bfloat16(v.x);
        __nv_bfloat16 h1 = __float2bfloat16(v.y);
        __nv_bfloat16 h2 = __float2bfloat16(v.z);
        __nv_bfloat16 h3 = __float2bfloat16(v.w);
        __nv_bfloat16 l0 = __float2bfloat16(v.x - __bfloat162float(h0));
        __nv_bfloat16 l1 = __float2bfloat16(v.y - __bfloat162float(h1));
        __nv_bfloat16 l2 = __float2bfloat16(v.z - __bfloat162float(h2));
        __nv_bfloat16 l3 = __float2bfloat16(v.w - __bfloat162float(h3));
        __nv_bfloat162* ph = (__nv_bfloat162*)g_Ah4;
        __nv_bfloat162* pl = (__nv_bfloat162*)g_Al4;
        ph[i * 2 + 0] = __nv_bfloat162{h0, h1};
        ph[i * 2 + 1] = __nv_bfloat162{h2, h3};
        pl[i * 2 + 0] = __nv_bfloat162{l0, l1};
        pl[i * 2 + 1] = __nv_bfloat162{l2, l3};
    } else {
        __shared__ float tile[32][33];
        const int bx = blockIdx.x - 1024;
        const int k0 = (bx & 127) * 32, n0 = (bx >> 7) * 32;
        const int t = threadIdx.x;
        const int nc = t & 31, kr0 = t >> 5;
#pragma unroll
        for (int i = 0; i < 4; ++i) {
            int kr = kr0 + i * 8;
            tile[kr][nc] = W1[(size_t)(k0 + kr) * DH + n0 + nc];
        }
        __syncthreads();
        const int i = t >> 3, j0 = (t & 7) * 4;
        __nv_bfloat16 hs[4], ls[4];
#pragma unroll
        for (int jj = 0; jj < 4; ++jj) {
            float x = tile[j0 + jj][i];
            __nv_bfloat16 h = __float2bfloat16(x);
            hs[jj] = h;
            ls[jj] = __float2bfloat16(x - __bfloat162float(h));
        }
        size_t off = (size_t)(n0 + i) * DV + k0 + j0;
        __nv_bfloat162* ph = (__nv_bfloat162*)((__nv_bfloat16*)g_Bh4 + off);
        __nv_bfloat162* pl = (__nv_bfloat162*)((__nv_bfloat16*)g_Bl4 + off);
        ph[0] = __nv_bfloat162{hs[0], hs[1]};
        ph[1] = __nv_bfloat162{hs[2], hs[3]};
        pl[0] = __nv_bfloat162{ls[0], ls[1]};
        pl[1] = __nv_bfloat162{ls[2], ls[3]};
    }
}

// ---------------------------------------------------------------------------
// gemm1_tc: g_hp[z][m][n] = A_slice @ B_slice with bf16 split-2 compensation
// CTA tile M64 x N128, 8 warps (2m x 4n), warp tile 32x32, K chunk 32.
// grid (8 n, 4 m, SPL1=8 z) = 256 CTAs; K-slice 512 = 16 chunks.
// ---------------------------------------------------------------------------
__global__ __launch_bounds__(256, 2) void gemm1_tc(int dummy)
{
    __shared__ unsigned short sAh[2][64][40], sAl[2][64][40];
    __shared__ unsigned short sBh[2][128][40], sBl[2][128][40];

    const int t = threadIdx.x;
    const int lane = t & 31, warp = t >> 5;
    const int g = lane >> 2, tq = lane & 3;
    const int wm = warp & 1, wn = warp >> 1;
    const int m0 = blockIdx.y * 64, n0 = blockIdx.x * 128;
    const size_t kb0 = (size_t)blockIdx.z * 512;

    const __nv_bfloat16* Ah = (const __nv_bfloat16*)g_Ah4;
    const __nv_bfloat16* Al = (const __nv_bfloat16*)g_Al4;
    const __nv_bfloat16* Bh = (const __nv_bfloat16*)g_Bh4;
    const __nv_bfloat16* Bl = (const __nv_bfloat16*)g_Bl4;

    const int ldRow  = t >> 2;            // 0..63
    const int ldPart = (t & 3) * 8;       // bf16 elems
    const size_t aOff  = (size_t)(m0 + ldRow) * DV + kb0 + ldPart;
    const size_t bOff1 = (size_t)(n0 + ldRow) * DV + kb0 + ldPart;
    const size_t bOff2 = (size_t)(n0 + 64 + ldRow) * DV + kb0 + ldPart;

    float d[2][4][4];
#pragma unroll
    for (int mf = 0; mf < 2; ++mf)
#pragma unroll
        for (int nf = 0; nf < 4; ++nf)
#pragma unroll
            for (int r = 0; r < 4; ++r) d[mf][nf][r] = 0.f;

    {
        uint4 pAh  = *(const uint4*)(Ah + aOff);
        uint4 pAl  = *(const uint4*)(Al + aOff);
        uint4 pB1h = *(const uint4*)(Bh + bOff1);
        uint4 pB2h = *(const uint4*)(Bh + bOff2);
        uint4 pB1l = *(const uint4*)(Bl + bOff1);
        uint4 pB2l = *(const uint4*)(Bl + bOff2);
        *(uint4*)&sAh[0][ldRow][ldPart] = pAh;
        *(uint4*)&sAl[0][ldRow][ldPart] = pAl;
        *(uint4*)&sBh[0][ldRow][ldPart] = pB1h;
        *(uint4*)&sBh[0][64 + ldRow][ldPart] = pB2h;
        *(uint4*)&sBl[0][ldRow][ldPart] = pB1l;
        *(uint4*)&sBl[0][64 + ldRow][ldPart] = pB2l;
    }
    __syncthreads();

    for (int c = 0; c < 16; ++c) {
        const int cur = c & 1;
        const int nxt = cur ^ 1;

        uint4 pAh, pAl, pB1h, pB2h, pB1l, pB2l;
        if (c < 15) {
            size_t kd = (size_t)(c + 1) * 32;
            pAh  = *(const uint4*)(Ah + aOff + kd);
            pAl  = *(const uint4*)(Al + aOff + kd);
            pB1h = *(const uint4*)(Bh + bOff1 + kd);
            pB2h = *(const uint4*)(Bh + bOff2 + kd);
            pB1l = *(const uint4*)(Bl + bOff1 + kd);
            pB2l = *(const uint4*)(Bl + bOff2 + kd);
        }

#pragma unroll
        for (int s = 0; s < 2; ++s) {
            const int kc = s * 16 + 2 * tq;
            unsigned ah[2][4], al[2][4], bh[4][2], bl[4][2];
#pragma unroll
            for (int mf = 0; mf < 2; ++mf) {
                int r = wm * 32 + mf * 16 + g;
                ah[mf][0] = *(const unsigned*)&sAh[cur][r][kc];
                ah[mf][1] = *(const unsigned*)&sAh[cur][r + 8][kc];
                ah[mf][2] = *(const unsigned*)&sAh[cur][r][kc + 8];
                ah[mf][3] = *(const unsigned*)&sAh[cur][r + 8][kc + 8];
                al[mf][0] = *(const unsigned*)&sAl[cur][r][kc];
                al[mf][1] = *(const unsigned*)&sAl[cur][r + 8][kc];
                al[mf][2] = *(const unsigned*)&sAl[cur][r][kc + 8];
                al[mf][3] = *(const unsigned*)&sAl[cur][r + 8][kc + 8];
            }
#pragma unroll
            for (int nf = 0; nf < 4; ++nf) {
                int n = wn * 32 + nf * 8 + g;
                bh[nf][0] = *(const unsigned*)&sBh[cur][n][kc];
                bh[nf][1] = *(const unsigned*)&sBh[cur][n][kc + 8];
                bl[nf][0] = *(const unsigned*)&sBl[cur][n][kc];
                bl[nf][1] = *(const unsigned*)&sBl[cur][n][kc + 8];
            }
#pragma unroll
            for (int nf = 0; nf < 4; ++nf)
#pragma unroll
                for (int mf = 0; mf < 2; ++mf)
                    mma_bf16(d[mf][nf], ah[mf], bh[nf]);
#pragma unroll
            for (int nf = 0; nf < 4; ++nf)
#pragma unroll
                for (int mf = 0; mf < 2; ++mf)
                    mma_bf16(d[mf][nf], ah[mf], bl[nf]);
#pragma unroll
            for (int nf = 0; nf < 4; ++nf)
#pragma unroll
                for (int mf = 0; mf < 2; ++mf)
                    mma_bf16(d[mf][nf], al[mf], bh[nf]);
        }

        if (c < 15) {
            *(uint4*)&sAh[nxt][ldRow][ldPart] = pAh;
            *(uint4*)&sAl[nxt][ldRow][ldPart] = pAl;
            *(uint4*)&sBh[nxt][ldRow][ldPart] = pB1h;
            *(uint4*)&sBh[nxt][64 + ldRow][ldPart] = pB2h;
            *(uint4*)&sBl[nxt][ldRow][ldPart] = pB1l;
            *(uint4*)&sBl[nxt][64 + ldRow][ldPart] = pB2l;
        }
        __syncthreads();
    }

    float* outp = g_hp[blockIdx.z];
#pragma unroll
    for (int mf = 0; mf < 2; ++mf)
#pragma unroll
        for (int nf = 0; nf < 4; ++nf) {
            int m = m0 + wm * 32 + mf * 16 + g;
            int n = n0 + wn * 32 + nf * 8 + 2 * tq;
            *(float2*)&outp[(size_t)m * DH + n] =
                make_float2(d[mf][nf][0], d[mf][nf][1]);
            *(float2*)&outp[(size_t)(m + 8) * DH + n] =
                make_float2(d[mf][nf][2], d[mf][nf][3]);
        }
}

// ---------------------------------------------------------------------------
// GEMM2: g_ep[s] = relu(sum_z g_hp[z] + b1) @ W2  over 64-wide k-slice s
// grid (16, SPL2=16) = 256 blocks
// ---------------------------------------------------------------------------
__global__ __launch_bounds__(256) void gemm2_kernel(
    const float* __restrict__ W2, const float* __restrict__ b1)
{
    __shared__ __align__(16) float sh_h[16 * 64];
    __shared__ float sh_w[64 * 112];

    const int t = threadIdx.x;
    const int m0 = blockIdx.x * 16;
    const int kc = blockIdx.y * 64;
    const int tm = t >> 4, tj = t & 15;

    float acc[7];
#pragma unroll
    for (int u = 0; u < 7; ++u) acc[u] = 0.f;

    {
        int idx = t * 4;
        int m = idx >> 6, kk = idx & 63;
        size_t off = (size_t)(m0 + m) * DH + kc + kk;
        float4 hv = *(const float4*)(b1 + kc + kk);
#pragma unroll
        for (int z = 0; z < SPL1; ++z) {
            float4 p = *(const float4*)(g_hp[z] + off);
            hv.x += p.x; hv.y += p.y; hv.z += p.z; hv.w += p.w;
        }
        hv.x = fmaxf(hv.x, 0.f);
        hv.y = fmaxf(hv.y, 0.f);
        hv.z = fmaxf(hv.z, 0.f);
        hv.w = fmaxf(hv.w, 0.f);
        *(float4*)&sh_h[m * 64 + kk] = hv;
    }
#pragma unroll
    for (int r = 0; r < 25; ++r) {
        int idx = r * 256 + t;
        int kk = idx / 100;
        int j  = idx - kk * 100;
        sh_w[kk * 112 + j] = W2[(size_t)(kc + kk) * DE + j];
    }
    __syncthreads();

#pragma unroll 8
    for (int kk = 0; kk < 64; ++kk) {
        float a = sh_h[tm * 64 + kk];
#pragma unroll
        for (int u = 0; u < 7; ++u)
            acc[u] += a * sh_w[kk * 112 + tj + 16 * u];
    }
    __syncthreads();

    float* ep = g_ep[blockIdx.y];
#pragma unroll
    for (int u = 0; u < 7; ++u) {
        int j = tj + 16 * u;
        if (j < DE) ep[(size_t)(m0 + tm) * DE + j] = acc[u];
    }
}

// ---------------------------------------------------------------------------
// finalize_e: g_eneg = -(b2 + sum_s g_ep[s]), float4-wide (6400 float4s)
// ---------------------------------------------------------------------------
__global__ __launch_bounds__(256) void finalize_e(const float* __restrict__ b2)
{
    int idx = blockIdx.x * 256 + threadIdx.x;     // 0..6399 (float4 index)
    int n = idx / 25;
    int d4 = idx - n * 25;
    float4 v = ((const float4*)b2)[d4];
#pragma unroll
    for (int s = 0; s < SPL2; ++s) {
        float4 p = ((const float4*)g_ep[s])[idx];
        v.x += p.x; v.y += p.y; v.z += p.z; v.w += p.w;
    }
    ((float4*)g_eneg)[idx] = make_float4(-v.x, -v.y, -v.z, -v.w);
}

// ---------------------------------------------------------------------------
// Scoring: out[n,l] = -sqrt( sum_d relu(lv[l,d] - e[n,d])^2 )
// Register tile 4l x 8n per thread. lv tile 256 l in smem (conflict-free
// LDS.128, 400B odd row stride); e tile 32 n in smem (warp-uniform LDS.128).
// threads: 64 l-groups x 4 n-groups. grid (79 l-tiles, 8 n-tiles) = 632.
// ---------------------------------------------------------------------------
__global__ __launch_bounds__(256, 2) void score_kernel(
    const float* __restrict__ lv, float* __restrict__ out)
{
    extern __shared__ __align__(16) float lvs[];   // [256][100] contiguous
    __shared__ __align__(16) float e_s[32 * DE];   // 12.8 KB

    const int t  = threadIdx.x;
    const int n0 = blockIdx.y * 32;
    const int l0 = blockIdx.x * 256;

    // e tile: 3200 floats = 800 float4 (contiguous copy)
    {
        const float4* src = (const float4*)(g_eneg + n0 * DE);
        float4* dst = (float4*)e_s;
#pragma unroll
        for (int idx = 0; idx < 3; ++idx) dst[t + idx * 256] = src[t + idx * 256];
        if (t < 32) dst[768 + t] = src[768 + t];
    }
    // lv tile: 256 rows x 400B = 6400 uint4, contiguous (25x16B = 400B rows)
    {
        const uint4* src = (const uint4*)(lv + (size_t)l0 * DE);
        uint4* dst = (uint4*)lvs;
        if (l0 + 256 <= LL) {
#pragma unroll
            for (int k = 0; k < 25; ++k)
                dst[t + k * 256] = src[t + k * 256];
        } else {
            const int maxu4 = (LL - l0) * 25;
#pragma unroll
            for (int k = 0; k < 25; ++k) {
                int i = t + k * 256;
                dst[i] = (i < maxu4) ? src[i] : make_uint4(0u, 0u, 0u, 0u);
            }
        }
    }
    __syncthreads();

    const int tl = t & 63;          // l-group: rows tl, tl+64, tl+128, tl+192
    const int ng = t >> 6;          // n-group: n = n0 + ng*8 + [0..7]

    const ulonglong2* row0 = (const ulonglong2*)(lvs + (tl +   0) * DE);
    const ulonglong2* row1 = (const ulonglong2*)(lvs + (tl +  64) * DE);
    const ulonglong2* row2 = (const ulonglong2*)(lvs + (tl + 128) * DE);
    const ulonglong2* row3 = (const ulonglong2*)(lvs + (tl + 192) * DE);
    const ulonglong2* eb   = (const ulonglong2*)(e_s + ng * 8 * DE);
    // per n row: 100 floats = 25 ulonglong2

    u64 acc[4][8];
#pragma unroll
    for (int k = 0; k < 4; ++k)
#pragma unroll
        for (int n = 0; n < 8; ++n) acc[k][n] = 0ull;

#pragma unroll 1
    for (int q = 0; q < 25; ++q) {
        ulonglong2 a0 = row0[q];
        ulonglong2 a1 = row1[q];
        ulonglong2 a2 = row2[q];
        ulonglong2 a3 = row3[q];
#pragma unroll
        for (int n = 0; n < 8; ++n) {
            ulonglong2 e4 = eb[n * 25 + q];   // warp-uniform LDS.128
            u64 t0, t1, t2, t3;
            t0 = f2relu(f2add(a0.x, e4.x)); acc[0][n] = f2fma(t0, t0, acc[0][n]);
            t1 = f2relu(f2add(a1.x, e4.x)); acc[1][n] = f2fma(t1, t1, acc[1][n]);
            t2 = f2relu(f2add(a2.x, e4.x)); acc[2][n] = f2fma(t2, t2, acc[2][n]);
            t3 = f2relu(f2add(a3.x, e4.x)); acc[3][n] = f2fma(t3, t3, acc[3][n]);
            t0 = f2relu(f2add(a0.y, e4.y)); acc[0][n] = f2fma(t0, t0, acc[0][n]);
            t1 = f2relu(f2add(a1.y, e4.y)); acc[1][n] = f2fma(t1, t1, acc[1][n]);
            t2 = f2relu(f2add(a2.y, e4.y)); acc[2][n] = f2fma(t2, t2, acc[2][n]);
            t3 = f2relu(f2add(a3.y, e4.y)); acc[3][n] = f2fma(t3, t3, acc[3][n]);
        }
    }

#pragma unroll
    for (int k = 0; k < 4; ++k) {
        const int l = l0 + tl + k * 64;
        if (l < LL) {
#pragma unroll
            for (int n = 0; n < 8; ++n) {
                float2 v = funpack(acc[k][n]);
                out[(size_t)(n0 + ng * 8 + n) * LL + l] = -fsqrt_ap(v.x + v.y);
            }
        }
    }
}

// ---------------------------------------------------------------------------
extern "C" void kernel_launch(void* const* d_in, const int* in_sizes, int n_in,
                              void* d_out, int out_size)
{
    const float* vfs = (const float*)d_in[0];   // [256, 4096]
    const float* lv  = (const float*)d_in[1];   // [20000, 100]
    const float* W1  = (const float*)d_in[2];   // [4096, 1024]
    const float* b1  = (const float*)d_in[3];   // [1024]
    const float* W2  = (const float*)d_in[4];   // [1024, 100]
    const float* b2  = (const float*)d_in[5];   // [100]
    float* out = (float*)d_out;                 // [256, 20000]

    const int lv_smem = 256 * DE * (int)sizeof(float);   // 102400 B
    cudaFuncSetAttribute(score_kernel,
                         cudaFuncAttributeMaxDynamicSharedMemorySize, lv_smem);

    prep_all<<<1024 + 4096, 256>>>(vfs, W1);
    gemm1_tc<<<dim3(8, 4, SPL1), 256>>>(0);
    gemm2_kernel<<<dim3(16, SPL2), 256>>>(W2, b1);
    finalize_e<<<25, 256>>>(b2);
    score_kernel<<<dim3(79, 8), 256, lv_smem>>>(lv, out);
}

// round 14
// speedup vs baseline: 1.4585x; 1.0459x over previous
#include <cuda_runtime.h>
#include <cuda_bf16.h>

// ---------------------------------------------------------------------------
// HypernymVisual: h = relu(vfs)@W1 + b1 ; e = relu(h)@W2 + b2 ;
// scores[n,l] = -sqrt(sum_d relu(lv[l,d] - e[n,d])^2)
//
// Round 14: score register tile NL=2 x NN=8 with 128-row lv tile (64KB/CTA)
// -> 3 CTAs/SM (6 warps/SMSP) to lift issue efficiency. finalize_e spread
// over 100 blocks.
// ---------------------------------------------------------------------------

#define NV   256
#define DV   4096
#define DH   1024
#define DE   100
#define LL   20000
#define SPL1 8      // gemm1 K splits (512 cols each)
#define SPL2 16     // gemm2 K splits (64 cols each)

typedef unsigned long long u64;

// scratch (device globals)
__device__ uint4 g_Ah4[NV * DV / 8];   // bf16 [256][4096]  hi(relu(vfs))
__device__ uint4 g_Al4[NV * DV / 8];   // bf16 [256][4096]  lo residual
__device__ uint4 g_Bh4[DH * DV / 8];   // bf16 [1024 n][4096 k]  hi(W1^T)
__device__ uint4 g_Bl4[DH * DV / 8];   // bf16 [1024 n][4096 k]  lo residual
__device__ float g_hp[SPL1][NV * DH];  // gemm1 K-split partials (no bias)
__device__ float g_ep[SPL2][NV * DE];  // gemm2 K-split partials (no bias)
__device__ __align__(16) float g_eneg[NV * DE];  // -(e) final embeddings

// ---- f32x2 helpers ---------------------------------------------------------
__device__ __forceinline__ u64 f2add(u64 a, u64 b) {
    u64 r; asm("add.rn.f32x2 %0,%1,%2;" : "=l"(r) : "l"(a), "l"(b)); return r;
}
__device__ __forceinline__ u64 f2fma(u64 a, u64 b, u64 c) {
    u64 r; asm("fma.rn.f32x2 %0,%1,%2,%3;" : "=l"(r) : "l"(a), "l"(b), "l"(c)); return r;
}
__device__ __forceinline__ u64 f2relu(u64 x) {
    u64 r;
    asm("{\n\t"
        ".reg .s32 lo, hi;\n\t"
        "mov.b64 {lo, hi}, %1;\n\t"
        "max.s32 lo, lo, 0;\n\t"
        "max.s32 hi, hi, 0;\n\t"
        "mov.b64 %0, {lo, hi};\n\t"
        "}" : "=l"(r) : "l"(x));
    return r;
}
__device__ __forceinline__ float2 funpack(u64 a) {
    unsigned lo, hi;
    asm("mov.b64 {%0,%1},%2;" : "=r"(lo), "=r"(hi) : "l"(a));
    return make_float2(__uint_as_float(lo), __uint_as_float(hi));
}
__device__ __forceinline__ float fsqrt_ap(float x) {
    float r; asm("sqrt.approx.f32 %0,%1;" : "=f"(r) : "f"(x)); return r;
}

// ---- bf16 mma --------------------------------------------------------------
__device__ __forceinline__ void mma_bf16(float d[4], const unsigned a[4],
                                         const unsigned b[2]) {
    asm("mma.sync.aligned.m16n8k16.row.col.f32.bf16.bf16.f32 "
        "{%0,%1,%2,%3},{%4,%5,%6,%7},{%8,%9},{%0,%1,%2,%3};"
        : "+f"(d[0]), "+f"(d[1]), "+f"(d[2]), "+f"(d[3])
        : "r"(a[0]), "r"(a[1]), "r"(a[2]), "r"(a[3]), "r"(b[0]), "r"(b[1]));
}

// ---------------------------------------------------------------------------
// prep_all: blocks [0,1024): A = relu(vfs) -> bf16 hi/lo, [m][k]
//           blocks [1024,5120): W1 -> transposed bf16 hi/lo [n][k]
// ---------------------------------------------------------------------------
__global__ __launch_bounds__(256) void prep_all(
    const float* __restrict__ vfs, const float* __restrict__ W1)
{
    if (blockIdx.x < 1024) {
        int i = blockIdx.x * 256 + threadIdx.x;        // float4 index
        float4 v = ((const float4*)vfs)[i];
        v.x = fmaxf(v.x, 0.f); v.y = fmaxf(v.y, 0.f);
        v.z = fmaxf(v.z, 0.f); v.w = fmaxf(v.w, 0.f);
        __nv_bfloat16 h0 = __float2bfloat16(v.x);
        __nv_bfloat16 h1 = __float2bfloat16(v.y);
        __nv_bfloat16 h2 = __float2bfloat16(v.z);
        __nv_bfloat16 h3 = __float2bfloat16(v.w);
        __nv_bfloat16 l0 = __float2bfloat16(v.x - __bfloat162float(h0));
        __nv_bfloat16 l1 = __float2bfloat16(v.y - __bfloat162float(h1));
        __nv_bfloat16 l2 = __float2bfloat16(v.z - __bfloat162float(h2));
        __nv_bfloat16 l3 = __float2bfloat16(v.w - __bfloat162float(h3));
        __nv_bfloat162* ph = (__nv_bfloat162*)g_Ah4;
        __nv_bfloat162* pl = (__nv_bfloat162*)g_Al4;
        ph[i * 2 + 0] = __nv_bfloat162{h0, h1};
        ph[i * 2 + 1] = __nv_bfloat162{h2, h3};
        pl[i * 2 + 0] = __nv_bfloat162{l0, l1};
        pl[i * 2 + 1] = __nv_bfloat162{l2, l3};
    } else {
        __shared__ float tile[32][33];
        const int bx = blockIdx.x - 1024;
        const int k0 = (bx & 127) * 32, n0 = (bx >> 7) * 32;
        const int t = threadIdx.x;
        const int nc = t & 31, kr0 = t >> 5;
#pragma unroll
        for (int i = 0; i < 4; ++i) {
            int kr = kr0 + i * 8;
            tile[kr][nc] = W1[(size_t)(k0 + kr) * DH + n0 + nc];
        }
        __syncthreads();
        const int i = t >> 3, j0 = (t & 7) * 4;
        __nv_bfloat16 hs[4], ls[4];
#pragma unroll
        for (int jj = 0; jj < 4; ++jj) {
            float x = tile[j0 + jj][i];
            __nv_bfloat16 h = __float2bfloat16(x);
            hs[jj] = h;
            ls[jj] = __float2bfloat16(x - __bfloat162float(h));
        }
        size_t off = (size_t)(n0 + i) * DV + k0 + j0;
        __nv_bfloat162* ph = (__nv_bfloat162*)((__nv_bfloat16*)g_Bh4 + off);
        __nv_bfloat162* pl = (__nv_bfloat162*)((__nv_bfloat16*)g_Bl4 + off);
        ph[0] = __nv_bfloat162{hs[0], hs[1]};
        ph[1] = __nv_bfloat162{hs[2], hs[3]};
        pl[0] = __nv_bfloat162{ls[0], ls[1]};
        pl[1] = __nv_bfloat162{ls[2], ls[3]};
    }
}

// ---------------------------------------------------------------------------
// gemm1_tc: g_hp[z][m][n] = A_slice @ B_slice with bf16 split-2 compensation
// CTA tile M64 x N128, 8 warps (2m x 4n), warp tile 32x32, K chunk 32.
// grid (8 n, 4 m, SPL1=8 z) = 256 CTAs; K-slice 512 = 16 chunks.
// ---------------------------------------------------------------------------
__global__ __launch_bounds__(256, 2) void gemm1_tc(int dummy)
{
    __shared__ unsigned short sAh[2][64][40], sAl[2][64][40];
    __shared__ unsigned short sBh[2][128][40], sBl[2][128][40];

    const int t = threadIdx.x;
    const int lane = t & 31, warp = t >> 5;
    const int g = lane >> 2, tq = lane & 3;
    const int wm = warp & 1, wn = warp >> 1;
    const int m0 = blockIdx.y * 64, n0 = blockIdx.x * 128;
    const size_t kb0 = (size_t)blockIdx.z * 512;

    const __nv_bfloat16* Ah = (const __nv_bfloat16*)g_Ah4;
    const __nv_bfloat16* Al = (const __nv_bfloat16*)g_Al4;
    const __nv_bfloat16* Bh = (const __nv_bfloat16*)g_Bh4;
    const __nv_bfloat16* Bl = (const __nv_bfloat16*)g_Bl4;

    const int ldRow  = t >> 2;            // 0..63
    const int ldPart = (t & 3) * 8;       // bf16 elems
    const size_t aOff  = (size_t)(m0 + ldRow) * DV + kb0 + ldPart;
    const size_t bOff1 = (size_t)(n0 + ldRow) * DV + kb0 + ldPart;
    const size_t bOff2 = (size_t)(n0 + 64 + ldRow) * DV + kb0 + ldPart;

    float d[2][4][4];
#pragma unroll
    for (int mf = 0; mf < 2; ++mf)
#pragma unroll
        for (int nf = 0; nf < 4; ++nf)
#pragma unroll
            for (int r = 0; r < 4; ++r) d[mf][nf][r] = 0.f;

    {
        uint4 pAh  = *(const uint4*)(Ah + aOff);
        uint4 pAl  = *(const uint4*)(Al + aOff);
        uint4 pB1h = *(const uint4*)(Bh + bOff1);
        uint4 pB2h = *(const uint4*)(Bh + bOff2);
        uint4 pB1l = *(const uint4*)(Bl + bOff1);
        uint4 pB2l = *(const uint4*)(Bl + bOff2);
        *(uint4*)&sAh[0][ldRow][ldPart] = pAh;
        *(uint4*)&sAl[0][ldRow][ldPart] = pAl;
        *(uint4*)&sBh[0][ldRow][ldPart] = pB1h;
        *(uint4*)&sBh[0][64 + ldRow][ldPart] = pB2h;
        *(uint4*)&sBl[0][ldRow][ldPart] = pB1l;
        *(uint4*)&sBl[0][64 + ldRow][ldPart] = pB2l;
    }
    __syncthreads();

    for (int c = 0; c < 16; ++c) {
        const int cur = c & 1;
        const int nxt = cur ^ 1;

        uint4 pAh, pAl, pB1h, pB2h, pB1l, pB2l;
        if (c < 15) {
            size_t kd = (size_t)(c + 1) * 32;
            pAh  = *(const uint4*)(Ah + aOff + kd);
            pAl  = *(const uint4*)(Al + aOff + kd);
            pB1h = *(const uint4*)(Bh + bOff1 + kd);
            pB2h = *(const uint4*)(Bh + bOff2 + kd);
            pB1l = *(const uint4*)(Bl + bOff1 + kd);
            pB2l = *(const uint4*)(Bl + bOff2 + kd);
        }

#pragma unroll
        for (int s = 0; s < 2; ++s) {
            const int kc = s * 16 + 2 * tq;
            unsigned ah[2][4], al[2][4], bh[4][2], bl[4][2];
#pragma unroll
            for (int mf = 0; mf < 2; ++mf) {
                int r = wm * 32 + mf * 16 + g;
                ah[mf][0] = *(const unsigned*)&sAh[cur][r][kc];
                ah[mf][1] = *(const unsigned*)&sAh[cur][r + 8][kc];
                ah[mf][2] = *(const unsigned*)&sAh[cur][r][kc + 8];
                ah[mf][3] = *(const unsigned*)&sAh[cur][r + 8][kc + 8];
                al[mf][0] = *(const unsigned*)&sAl[cur][r][kc];
                al[mf][1] = *(const unsigned*)&sAl[cur][r + 8][kc];
                al[mf][2] = *(const unsigned*)&sAl[cur][r][kc + 8];
                al[mf][3] = *(const unsigned*)&sAl[cur][r + 8][kc + 8];
            }
#pragma unroll
            for (int nf = 0; nf < 4; ++nf) {
                int n = wn * 32 + nf * 8 + g;
                bh[nf][0] = *(const unsigned*)&sBh[cur][n][kc];
                bh[nf][1] = *(const unsigned*)&sBh[cur][n][kc + 8];
                bl[nf][0] = *(const unsigned*)&sBl[cur][n][kc];
                bl[nf][1] = *(const unsigned*)&sBl[cur][n][kc + 8];
            }
#pragma unroll
            for (int nf = 0; nf < 4; ++nf)
#pragma unroll
                for (int mf = 0; mf < 2; ++mf)
                    mma_bf16(d[mf][nf], ah[mf], bh[nf]);
#pragma unroll
            for (int nf = 0; nf < 4; ++nf)
#pragma unroll
                for (int mf = 0; mf < 2; ++mf)
                    mma_bf16(d[mf][nf], ah[mf], bl[nf]);
#pragma unroll
            for (int nf = 0; nf < 4; ++nf)
#pragma unroll
                for (int mf = 0; mf < 2; ++mf)
                    mma_bf16(d[mf][nf], al[mf], bh[nf]);
        }

        if (c < 15) {
            *(uint4*)&sAh[nxt][ldRow][ldPart] = pAh;
            *(uint4*)&sAl[nxt][ldRow][ldPart] = pAl;
            *(uint4*)&sBh[nxt][ldRow][ldPart] = pB1h;
            *(uint4*)&sBh[nxt][64 + ldRow][ldPart] = pB2h;
            *(uint4*)&sBl[nxt][ldRow][ldPart] = pB1l;
            *(uint4*)&sBl[nxt][64 + ldRow][ldPart] = pB2l;
        }
        __syncthreads();
    }

    float* outp = g_hp[blockIdx.z];
#pragma unroll
    for (int mf = 0; mf < 2; ++mf)
#pragma unroll
        for (int nf = 0; nf < 4; ++nf) {
            int m = m0 + wm * 32 + mf * 16 + g;
            int n = n0 + wn * 32 + nf * 8 + 2 * tq;
            *(float2*)&outp[(size_t)m * DH + n] =
                make_float2(d[mf][nf][0], d[mf][nf][1]);
            *(float2*)&outp[(size_t)(m + 8) * DH + n] =
                make_float2(d[mf][nf][2], d[mf][nf][3]);
        }
}

// ---------------------------------------------------------------------------
// GEMM2: g_ep[s] = relu(sum_z g_hp[z] + b1) @ W2  over 64-wide k-slice s
// grid (16, SPL2=16) = 256 blocks
// ---------------------------------------------------------------------------
__global__ __launch_bounds__(256) void gemm2_kernel(
    const float* __restrict__ W2, const float* __restrict__ b1)
{
    __shared__ __align__(16) float sh_h[16 * 64];
    __shared__ float sh_w[64 * 112];

    const int t = threadIdx.x;
    const int m0 = blockIdx.x * 16;
    const int kc = blockIdx.y * 64;
    const int tm = t >> 4, tj = t & 15;

    float acc[7];
#pragma unroll
    for (int u = 0; u < 7; ++u) acc[u] = 0.f;

    {
        int idx = t * 4;
        int m = idx >> 6, kk = idx & 63;
        size_t off = (size_t)(m0 + m) * DH + kc + kk;
        float4 hv = *(const float4*)(b1 + kc + kk);
#pragma unroll
        for (int z = 0; z < SPL1; ++z) {
            float4 p = *(const float4*)(g_hp[z] + off);
            hv.x += p.x; hv.y += p.y; hv.z += p.z; hv.w += p.w;
        }
        hv.x = fmaxf(hv.x, 0.f);
        hv.y = fmaxf(hv.y, 0.f);
        hv.z = fmaxf(hv.z, 0.f);
        hv.w = fmaxf(hv.w, 0.f);
        *(float4*)&sh_h[m * 64 + kk] = hv;
    }
#pragma unroll
    for (int r = 0; r < 25; ++r) {
        int idx = r * 256 + t;
        int kk = idx / 100;
        int j  = idx - kk * 100;
        sh_w[kk * 112 + j] = W2[(size_t)(kc + kk) * DE + j];
    }
    __syncthreads();

#pragma unroll 8
    for (int kk = 0; kk < 64; ++kk) {
        float a = sh_h[tm * 64 + kk];
#pragma unroll
        for (int u = 0; u < 7; ++u)
            acc[u] += a * sh_w[kk * 112 + tj + 16 * u];
    }
    __syncthreads();

    float* ep = g_ep[blockIdx.y];
#pragma unroll
    for (int u = 0; u < 7; ++u) {
        int j = tj + 16 * u;
        if (j < DE) ep[(size_t)(m0 + tm) * DE + j] = acc[u];
    }
}

// ---------------------------------------------------------------------------
// finalize_e: g_eneg = -(b2 + sum_s g_ep[s]), float4-wide (6400 float4s)
// grid 100 blocks x 64 threads (spread across SMs)
// ---------------------------------------------------------------------------
__global__ __launch_bounds__(64) void finalize_e(const float* __restrict__ b2)
{
    int idx = blockIdx.x * 64 + threadIdx.x;      // 0..6399 (float4 index)
    int n = idx / 25;
    int d4 = idx - n * 25;
    float4 v = ((const float4*)b2)[d4];
#pragma unroll
    for (int s = 0; s < SPL2; ++s) {
        float4 p = ((const float4*)g_ep[s])[idx];
        v.x += p.x; v.y += p.y; v.z += p.z; v.w += p.w;
    }
    ((float4*)g_eneg)[idx] = make_float4(-v.x, -v.y, -v.z, -v.w);
}

// ---------------------------------------------------------------------------
// Scoring: out[n,l] = -sqrt( sum_d relu(lv[l,d] - e[n,d])^2 )
// Register tile 2l x 8n per thread. lv tile 128 l (51.2KB smem) + e 32 n
// (12.8KB) = 64KB/CTA -> 3 CTAs/SM. threads: 64 l-groups x 4 n-groups.
// grid (157 l-tiles, 8 n-tiles) = 1256 blocks.
// ---------------------------------------------------------------------------
__global__ __launch_bounds__(256, 3) void score_kernel(
    const float* __restrict__ lv, float* __restrict__ out)
{
    extern __shared__ __align__(16) float lvs[];   // [128][100] contiguous
    __shared__ __align__(16) float e_s[32 * DE];   // 12.8 KB

    const int t  = threadIdx.x;
    const int n0 = blockIdx.y * 32;
    const int l0 = blockIdx.x * 128;

    // e tile: 3200 floats = 800 float4 (contiguous copy)
    {
        const float4* src = (const float4*)(g_eneg + n0 * DE);
        float4* dst = (float4*)e_s;
#pragma unroll
        for (int idx = 0; idx < 3; ++idx) dst[t + idx * 256] = src[t + idx * 256];
        if (t < 32) dst[768 + t] = src[768 + t];
    }
    // lv tile: 128 rows x 400B = 3200 uint4, contiguous
    {
        const uint4* src = (const uint4*)(lv + (size_t)l0 * DE);
        uint4* dst = (uint4*)lvs;
        if (l0 + 128 <= LL) {
#pragma unroll
            for (int k = 0; k < 12; ++k)
                dst[t + k * 256] = src[t + k * 256];
            if (t < 128) dst[t + 3072] = src[t + 3072];
        } else {
            const int maxu4 = (LL - l0) * 25;
#pragma unroll
            for (int k = 0; k < 12; ++k) {
                int i = t + k * 256;
                dst[i] = (i < maxu4) ? src[i] : make_uint4(0u, 0u, 0u, 0u);
            }
            if (t < 128) {
                int i = t + 3072;
                dst[i] = (i < maxu4) ? src[i] : make_uint4(0u, 0u, 0u, 0u);
            }
        }
    }
    __syncthreads();

    const int tl = t & 63;          // l-group: rows tl, tl+64
    const int ng = t >> 6;          // n-group: n = n0 + ng*8 + [0..7]

    const ulonglong2* row0 = (const ulonglong2*)(lvs + (tl +  0) * DE);
    const ulonglong2* row1 = (const ulonglong2*)(lvs + (tl + 64) * DE);
    const ulonglong2* eb   = (const ulonglong2*)(e_s + ng * 8 * DE);
    // per n row: 100 floats = 25 ulonglong2

    u64 acc[2][8];
#pragma unroll
    for (int k = 0; k < 2; ++k)
#pragma unroll
        for (int n = 0; n < 8; ++n) acc[k][n] = 0ull;

#pragma unroll 1
    for (int q = 0; q < 25; ++q) {
        ulonglong2 a0 = row0[q];
        ulonglong2 a1 = row1[q];
#pragma unroll
        for (int n = 0; n < 8; ++n) {
            ulonglong2 e4 = eb[n * 25 + q];   // warp-uniform LDS.128
            u64 t0, t1;
            t0 = f2relu(f2add(a0.x, e4.x)); acc[0][n] = f2fma(t0, t0, acc[0][n]);
            t1 = f2relu(f2add(a1.x, e4.x)); acc[1][n] = f2fma(t1, t1, acc[1][n]);
            t0 = f2relu(f2add(a0.y, e4.y)); acc[0][n] = f2fma(t0, t0, acc[0][n]);
            t1 = f2relu(f2add(a1.y, e4.y)); acc[1][n] = f2fma(t1, t1, acc[1][n]);
        }
    }

#pragma unroll
    for (int k = 0; k < 2; ++k) {
        const int l = l0 + tl + k * 64;
        if (l < LL) {
#pragma unroll
            for (int n = 0; n < 8; ++n) {
                float2 v = funpack(acc[k][n]);
                out[(size_t)(n0 + ng * 8 + n) * LL + l] = -fsqrt_ap(v.x + v.y);
            }
        }
    }
}

// ---------------------------------------------------------------------------
extern "C" void kernel_launch(void* const* d_in, const int* in_sizes, int n_in,
                              void* d_out, int out_size)
{
    const float* vfs = (const float*)d_in[0];   // [256, 4096]
    const float* lv  = (const float*)d_in[1];   // [20000, 100]
    const float* W1  = (const float*)d_in[2];   // [4096, 1024]
    const float* b1  = (const float*)d_in[3];   // [1024]
    const float* W2  = (const float*)d_in[4];   // [1024, 100]
    const float* b2  = (const float*)d_in[5];   // [100]
    float* out = (float*)d_out;                 // [256, 20000]

    const int lv_smem = 128 * DE * (int)sizeof(float);   // 51200 B
    cudaFuncSetAttribute(score_kernel,
                         cudaFuncAttributeMaxDynamicSharedMemorySize, lv_smem);

    prep_all<<<1024 + 4096, 256>>>(vfs, W1);
    gemm1_tc<<<dim3(8, 4, SPL1), 256>>>(0);
    gemm2_kernel<<<dim3(16, SPL2), 256>>>(W2, b1);
    finalize_e<<<100, 64>>>(b2);
    score_kernel<<<dim3(157, 8), 256, lv_smem>>>(lv, out);
}